// round 16
// baseline (speedup 1.0000x reference)
#include <cuda_runtime.h>
#include <cuda_fp16.h>
#include <stdint.h>

#define CH 64
#define HH 224
#define WW 224
#define HW (HH*WW)

#define TPX 32          // output tile width
#define TRY 8           // output tile rows
#define IR  10          // staged input rows (y0-1 .. y0+8)
#define IWS 40          // smem plane pitch in px (34 used; 40 keeps 8-px phase alignment)

#define PLANE_B (IR*IWS*128)                // 51200
#define OFF_WB  ((uint32_t)PLANE_B)         // weight kw-slice ring: 2 x 24576 B
#define WSLICE  24576u
#define SMEM_DYN (PLANE_B + 2*WSLICE)       // 100352 B -> 2 CTAs/SM

#define XP 226                              // padded H/W dims of g_xh

// Padded, pre-swizzled fp16 input: [n][Y][X][ci], 128 B per (Y,X).
// 16B ci-group s stored at slot s ^ (X & 7)  -> contiguous cp.async lands swizzled in smem.
// Pad cells (Y or X in {0,225}) are never written: zero-initialized => conv zero-padding.
__device__ __half g_xh[(size_t)32 * XP * XP * 64];   // 209 MB scratch

// B fragments in mma.m16n8k16.f16 fragment order, kw-major slices:
// [kw][kh][c][wn][half][lane]; half0 = {g0,g1}, half1 = {g2,g3} (g rel. to wn*32)
__device__ uint4 g_wf[3 * 3 * 4 * 2 * 2 * 32];   // 73728 B (L2-resident)

__global__ void prep_wfrag(const float* __restrict__ w) {
    int idx = blockIdx.x * blockDim.x + threadIdx.x;
    if (idx >= 3 * 3 * 4 * 2 * 2 * 32) return;
    int lane = idx & 31;
    int half = (idx >> 5) & 1;
    int wn   = (idx >> 6) & 1;
    int c    = (idx >> 7) & 3;
    int kh   = (idx >> 9) % 3;
    int kw   = idx / (3 * 512);
    int tap  = kh * 3 + kw;
    uint32_t r[4];
#pragma unroll
    for (int j = 0; j < 4; j++) {
        int g  = half * 2 + (j >> 1);
        int r2 = j & 1;
        int n  = wn * 32 + g * 8 + (lane >> 2);
        int k  = c * 16 + (lane & 3) * 2 + r2 * 8;
        float v0 = w[(n * 64 + k)     * 9 + tap];
        float v1 = w[(n * 64 + k + 1) * 9 + tap];
        float s0 = (v0 > 0.f) ? 1.f : ((v0 < 0.f) ? -1.f : 0.f);
        float s1 = (v1 > 0.f) ? 1.f : ((v1 < 0.f) ? -1.f : 0.f);
        __half h0 = __float2half(s0), h1 = __float2half(s1);
        r[j] = (uint32_t)__half_as_ushort(h0) | ((uint32_t)__half_as_ushort(h1) << 16);
    }
    g_wf[idx] = make_uint4(r[0], r[1], r[2], r[3]);
}

// NCHW fp32 -> padded pre-swizzled fp16. One thread per (n, gy, gx).
__global__ void __launch_bounds__(256)
conv_x(const float* __restrict__ x) {
    int t = blockIdx.x * 256 + threadIdx.x;      // 0 .. 32*224*224-1 (exact)
    int gx = t % WW;
    int rest = t / WW;
    int gy = rest % HH;
    int n  = rest / HH;
    const float* px = x + (size_t)n * CH * HW + (size_t)gy * WW + gx;
    int X = gx + 1, Y = gy + 1;
    int phi = X & 7;
    uint32_t* dst = (uint32_t*)(g_xh + (((size_t)n * XP + Y) * XP + X) * 64);
#pragma unroll
    for (int s = 0; s < 8; s++) {
        float v[8];
#pragma unroll
        for (int j = 0; j < 8; j++)
            v[j] = __ldg(px + (size_t)(8 * s + j) * HW);
        uint32_t u[4];
#pragma unroll
        for (int j = 0; j < 4; j++) {
            __half a = __float2half(v[2 * j]), b = __float2half(v[2 * j + 1]);
            u[j] = (uint32_t)__half_as_ushort(a) | ((uint32_t)__half_as_ushort(b) << 16);
        }
        uint4* o = (uint4*)(dst + (size_t)(s ^ phi) * 4);
        *o = make_uint4(u[0], u[1], u[2], u[3]);
    }
}

__device__ __forceinline__ uint32_t smem_u32(const void* p) {
    uint32_t a;
    asm("{ .reg .u64 t; cvta.to.shared.u64 t, %1; cvt.u32.u64 %0, t; }" : "=r"(a) : "l"(p));
    return a;
}
__device__ __forceinline__ uint32_t swz(uint32_t off) {   // SW128-atom XOR swizzle
    return off ^ ((off >> 3) & 0x70);
}
__device__ __forceinline__ void cpasync16(uint32_t dst, const void* src) {
    asm volatile("cp.async.cg.shared.global [%0], [%1], 16;" :: "r"(dst), "l"(src));
}
__device__ __forceinline__ void cpasync_commit() {
    asm volatile("cp.async.commit_group;");
}
__device__ __forceinline__ void cpasync_wait0() {
    asm volatile("cp.async.wait_group 0;");
}
__device__ __forceinline__ uint4 lds128(uint32_t a) {
    uint4 v;
    asm volatile("ld.shared.v4.b32 {%0,%1,%2,%3}, [%4];"
                 : "=r"(v.x), "=r"(v.y), "=r"(v.z), "=r"(v.w) : "r"(a));
    return v;
}
__device__ __forceinline__ void ldm_x4(uint32_t& r0, uint32_t& r1, uint32_t& r2, uint32_t& r3,
                                       uint32_t addr) {
    asm volatile("ldmatrix.sync.aligned.m8n8.x4.shared.b16 {%0,%1,%2,%3}, [%4];"
                 : "=r"(r0), "=r"(r1), "=r"(r2), "=r"(r3) : "r"(addr));
}
__device__ __forceinline__ void mma16816(float* d, const uint32_t* a, uint32_t b0, uint32_t b1) {
    asm volatile("mma.sync.aligned.m16n8k16.row.col.f32.f16.f16.f32 "
                 "{%0,%1,%2,%3},{%4,%5,%6,%7},{%8,%9},{%0,%1,%2,%3};"
                 : "+f"(d[0]), "+f"(d[1]), "+f"(d[2]), "+f"(d[3])
                 : "r"(a[0]), "r"(a[1]), "r"(a[2]), "r"(a[3]), "r"(b0), "r"(b1));
}

__global__ void __launch_bounds__(256, 2)
bconv_mma(const float* __restrict__ x, const float* __restrict__ bias,
          float* __restrict__ out)
{
    extern __shared__ char smraw[];
    const uint32_t smb = smem_u32(smraw);
    const int tid = threadIdx.x, lane = tid & 31, wid = tid >> 5;
    const int n = blockIdx.z, x0 = blockIdx.x * TPX, y0 = blockIdx.y * TRY;

    // ---- prime weight kw-slice 0 -> buf 0 via cp.async (1536 x 16B) ----
#pragma unroll
    for (int i = tid; i < 1536; i += 256)
        cpasync16(smb + OFF_WB + (uint32_t)i * 16u, g_wf + i);

    // ---- stage input plane via cp.async: 10 rows x 34 px x 8 slots = 2720 x 16B ----
    // g_xh is pre-swizzled; contiguous copy lands in swizzled smem layout.
    const char* xs = (const char*)(g_xh + (((size_t)n * XP + y0) * XP + x0) * 64);
#pragma unroll
    for (int it = 0; it < 11; it++) {
        int i = tid + it * 256;
        if (i < 2720) {
            int r = i / 272, rem = i - r * 272;
            cpasync16(smb + (uint32_t)(r * (IWS * 128) + rem * 16),
                      xs + (size_t)r * (XP * 128) + (uint32_t)rem * 16u);
        }
    }
    cpasync_commit();
    cpasync_wait0();
    __syncthreads();

    // ---- warp tiling: 4(M) x 2(N); warp tile M64 x N32 ----
    const int wn = wid & 1;          // co half
    const int wm = wid >> 1;         // pixel quarter: output rows {2wm, 2wm+1}

    const uint32_t acol = ((uint32_t)lane >> 4) * 16u;    // k-halves for A
    const uint32_t alx  = (uint32_t)(lane & 15);
    const uint32_t bln  = (uint32_t)wn * 1024u + (uint32_t)lane * 16u;

    float acc[4][4][4];               // [f=dy*2+xh][g][reg]
#pragma unroll
    for (int f = 0; f < 4; f++)
#pragma unroll
        for (int g = 0; g < 4; g++)
#pragma unroll
            for (int r = 0; r < 4; r++) acc[f][g][r] = 0.f;

#pragma unroll
    for (int kw = 0; kw < 3; kw++) {
        // prefetch next kw slice into the other ring buffer
        if (kw + 1 < 3) {
            const uint4* wp = g_wf + (size_t)(kw + 1) * 1536;
            uint32_t dst = smb + OFF_WB + (uint32_t)((kw + 1) & 1) * WSLICE;
#pragma unroll
            for (int i = tid; i < 1536; i += 256)
                cpasync16(dst + (uint32_t)i * 16u, wp + i);
            cpasync_commit();
        }

        const uint32_t wbuf = smb + OFF_WB + (uint32_t)(kw & 1) * WSLICE + bln;
#pragma unroll
        for (int c = 0; c < 4; c++) {
            // hoisted A: 8 fragments covering input rows 2wm..2wm+3, both xh chunks
            uint32_t A[4][2][4];
#pragma unroll
            for (int rr = 0; rr < 4; rr++)
#pragma unroll
                for (int xh = 0; xh < 2; xh++) {
                    uint32_t off = ((uint32_t)((2 * wm + rr) * IWS + kw)
                                   + alx + (uint32_t)(xh * 16)) * 128u
                                 + (uint32_t)c * 32u + acol;
                    ldm_x4(A[rr][xh][0], A[rr][xh][1], A[rr][xh][2], A[rr][xh][3],
                           smb + swz(off));
                }
#pragma unroll
            for (int kh = 0; kh < 3; kh++) {
                const uint32_t cb = wbuf + (uint32_t)kh * 8192u + (uint32_t)c * 2048u;
                uint4 B0 = lds128(cb);           // half0: g0,g1
                uint4 B1 = lds128(cb + 512u);    // half1: g2,g3
#pragma unroll
                for (int dy = 0; dy < 2; dy++) {
                    const int rr = kh + dy;
#pragma unroll
                    for (int xh = 0; xh < 2; xh++) {
                        const int f = dy * 2 + xh;
                        mma16816(acc[f][0], A[rr][xh], B0.x, B0.y);
                        mma16816(acc[f][1], A[rr][xh], B0.z, B0.w);
                        mma16816(acc[f][2], A[rr][xh], B1.x, B1.y);
                        mma16816(acc[f][3], A[rr][xh], B1.z, B1.w);
                    }
                }
            }
        }
        cpasync_wait0();
        __syncthreads();   // ring rotation: next slice visible, old slice free
    }

    // ---- epilogue: bias + store ----
    const int r0 = lane >> 2, c0 = (lane & 3) * 2;
    float bl[4], bh[4];
#pragma unroll
    for (int g = 0; g < 4; g++) {
        int co = wn * 32 + g * 8 + c0;
        bl[g] = __ldg(bias + co);
        bh[g] = __ldg(bias + co + 1);
    }
#pragma unroll
    for (int f = 0; f < 4; f++) {
        int y  = y0 + 2 * wm + (f >> 1);
        int xb = x0 + (f & 1) * 16;
#pragma unroll
        for (int g = 0; g < 4; g++) {
            int co = wn * 32 + g * 8 + c0;
            float* o0 = out + (((size_t)n * CH + co)     * HH + y) * WW + xb;
            float* o1 = out + (((size_t)n * CH + co + 1) * HH + y) * WW + xb;
            o0[r0]     = acc[f][g][0] + bl[g];
            o1[r0]     = acc[f][g][1] + bh[g];
            o0[r0 + 8] = acc[f][g][2] + bl[g];
            o1[r0 + 8] = acc[f][g][3] + bh[g];
        }
    }
}

extern "C" void kernel_launch(void* const* d_in, const int* in_sizes, int n_in,
                              void* d_out, int out_size) {
    const float* x    = (const float*)d_in[0];   // [32,64,224,224]
    const float* w    = (const float*)d_in[1];   // [64,64,3,3]
    const float* bias = (const float*)d_in[2];   // [64]
    float* out = (float*)d_out;

    conv_x<<<32 * HH * WW / 256, 256>>>(x);                  // 6272 blocks
    prep_wfrag<<<(3 * 3 * 4 * 2 * 2 * 32 + 255) / 256, 256>>>(w);

    cudaFuncSetAttribute(bconv_mma, cudaFuncAttributeMaxDynamicSharedMemorySize, SMEM_DYN);
    dim3 grid(WW / TPX, HH / TRY, 32);   // (7, 28, 32) = 6272 CTAs
    bconv_mma<<<grid, 256, SMEM_DYN>>>(x, bias, out);
}

// round 17
// speedup vs baseline: 1.3297x; 1.3297x over previous
#include <cuda_runtime.h>
#include <cuda_fp16.h>
#include <stdint.h>

#define CH 64
#define HH 224
#define WW 224
#define HW (HH*WW)

#define TPX 32          // output tile width
#define TRY 4           // output tile rows
#define IW  34          // staged input width (x0-1 .. x0+32)
#define IR2 6           // staged input rows  (y0-1 .. y0+4)

#define P_BYTES (IR2*IW*128)                // 27264: fp16 plane [(r,q)][ci 0..63]
#define OFF_WB  ((uint32_t)P_BYTES)         // single weight kw-slice: 24576 B
#define WSLICE  24576u
#define SMEM_DYN (P_BYTES + WSLICE)         // 51840 B -> 3 CTAs/SM

// B fragments in mma.m16n8k16.f16 fragment order, kw-major slices:
// [kw][kh][c][wn][half][lane]; half0 = {g0,g1}, half1 = {g2,g3} (g rel. to wn*32)
// lane holds {B[k][n], B[k+1][n]}, n = wn*32+g*8+lane/4, k = 16c+(lane%4)*2+r2*8
__device__ uint4 g_wf[3 * 3 * 4 * 2 * 2 * 32];   // 73728 B (L2-resident)

__global__ void prep_wfrag(const float* __restrict__ w) {
    int idx = blockIdx.x * blockDim.x + threadIdx.x;
    if (idx >= 3 * 3 * 4 * 2 * 2 * 32) return;
    int lane = idx & 31;
    int half = (idx >> 5) & 1;
    int wn   = (idx >> 6) & 1;
    int c    = (idx >> 7) & 3;
    int kh   = (idx >> 9) % 3;
    int kw   = idx / (3 * 512);
    int tap  = kh * 3 + kw;
    uint32_t r[4];
#pragma unroll
    for (int j = 0; j < 4; j++) {
        int g  = half * 2 + (j >> 1);
        int r2 = j & 1;
        int n  = wn * 32 + g * 8 + (lane >> 2);
        int k  = c * 16 + (lane & 3) * 2 + r2 * 8;
        float v0 = w[(n * 64 + k)     * 9 + tap];
        float v1 = w[(n * 64 + k + 1) * 9 + tap];
        float s0 = (v0 > 0.f) ? 1.f : ((v0 < 0.f) ? -1.f : 0.f);
        float s1 = (v1 > 0.f) ? 1.f : ((v1 < 0.f) ? -1.f : 0.f);
        __half h0 = __float2half(s0), h1 = __float2half(s1);
        r[j] = (uint32_t)__half_as_ushort(h0) | ((uint32_t)__half_as_ushort(h1) << 16);
    }
    g_wf[idx] = make_uint4(r[0], r[1], r[2], r[3]);
}

__device__ __forceinline__ uint32_t smem_u32(const void* p) {
    uint32_t a;
    asm("{ .reg .u64 t; cvta.to.shared.u64 t, %1; cvt.u32.u64 %0, t; }" : "=r"(a) : "l"(p));
    return a;
}
__device__ __forceinline__ uint32_t swz(uint32_t off) {   // SW128-atom XOR swizzle
    return off ^ ((off >> 3) & 0x70);
}
__device__ __forceinline__ void sts32(uint32_t a, uint32_t v) {
    asm volatile("st.shared.b32 [%0], %1;" :: "r"(a), "r"(v));
}
__device__ __forceinline__ void cpasync16(uint32_t dst, const void* src) {
    asm volatile("cp.async.cg.shared.global [%0], [%1], 16;" :: "r"(dst), "l"(src));
}
__device__ __forceinline__ void cpasync_commit() {
    asm volatile("cp.async.commit_group;");
}
__device__ __forceinline__ void cpasync_wait0() {
    asm volatile("cp.async.wait_group 0;");
}
__device__ __forceinline__ uint4 lds128(uint32_t a) {
    uint4 v;
    asm volatile("ld.shared.v4.b32 {%0,%1,%2,%3}, [%4];"
                 : "=r"(v.x), "=r"(v.y), "=r"(v.z), "=r"(v.w) : "r"(a));
    return v;
}
__device__ __forceinline__ void ldm_x4(uint32_t& r0, uint32_t& r1, uint32_t& r2, uint32_t& r3,
                                       uint32_t addr) {
    asm volatile("ldmatrix.sync.aligned.m8n8.x4.shared.b16 {%0,%1,%2,%3}, [%4];"
                 : "=r"(r0), "=r"(r1), "=r"(r2), "=r"(r3) : "r"(addr));
}
__device__ __forceinline__ void mma16816(float* d, const uint32_t* a, uint32_t b0, uint32_t b1) {
    asm volatile("mma.sync.aligned.m16n8k16.row.col.f32.f16.f16.f32 "
                 "{%0,%1,%2,%3},{%4,%5,%6,%7},{%8,%9},{%0,%1,%2,%3};"
                 : "+f"(d[0]), "+f"(d[1]), "+f"(d[2]), "+f"(d[3])
                 : "r"(a[0]), "r"(a[1]), "r"(a[2]), "r"(a[3]), "r"(b0), "r"(b1));
}

__global__ void __launch_bounds__(256, 3)
bconv_mma(const float* __restrict__ x, const float* __restrict__ bias,
          float* __restrict__ out)
{
    extern __shared__ char smraw[];
    const uint32_t smb = smem_u32(smraw);
    const int tid = threadIdx.x, lane = tid & 31, wid = tid >> 5;
    const int n = blockIdx.z, x0 = blockIdx.x * TPX, y0 = blockIdx.y * TRY;

    // ---- prime weight kw-slice 0 via cp.async (1536 x 16B), overlaps staging LDGs ----
#pragma unroll
    for (int i = tid; i < 1536; i += 256)
        cpasync16(smb + OFF_WB + (uint32_t)i * 16u, g_wf + i);
    cpasync_commit();

    // ---- stage fp16 input plane: (6 rows x 34 px) x 32 ci-pairs ----
    const float* xn = x + (size_t)n * CH * HW;
    for (int idx = tid; idx < IR2 * IW * 32; idx += 256) {
        int q  = idx % IW;
        int rc = idx / IW;
        int r  = rc % IR2;
        int cp = rc / IR2;                // ci pair 0..31
        int gx = x0 - 1 + q, ry = y0 - 1 + r;
        float v0 = 0.f, v1 = 0.f;
        if (gx >= 0 && gx < WW && ry >= 0 && ry < HH) {
            const float* p = xn + (size_t)(cp * 2) * HW + (size_t)ry * WW + gx;
            v0 = __ldg(p);
            v1 = __ldg(p + HW);
        }
        __half h0 = __float2half(v0), h1 = __float2half(v1);
        uint32_t hp = (uint32_t)__half_as_ushort(h0) | ((uint32_t)__half_as_ushort(h1) << 16);
        sts32(smb + swz((uint32_t)(r * IW + q) * 128u + (uint32_t)cp * 4u), hp);
    }
    cpasync_wait0();
    __syncthreads();

    // ---- warp tiling: 4(M) x 2(N); warp tile M32 x N32 ----
    const int wn = wid & 1;          // co half
    const int wm = wid >> 1;         // output row y0 + wm

    const uint32_t acol = ((uint32_t)lane >> 4) * 16u;    // k-halves for A
    const uint32_t alx  = (uint32_t)(lane & 15);
    const uint32_t bln  = (uint32_t)wn * 1024u + (uint32_t)lane * 16u;

    float acc[2][4][4];               // [xh][g][reg]
#pragma unroll
    for (int xh = 0; xh < 2; xh++)
#pragma unroll
        for (int g = 0; g < 4; g++)
#pragma unroll
            for (int r = 0; r < 4; r++) acc[xh][g][r] = 0.f;

#pragma unroll
    for (int kw = 0; kw < 3; kw++) {
        const uint32_t wbuf = smb + OFF_WB + bln;
#pragma unroll
        for (int c = 0; c < 4; c++) {
            // hoisted A: 6 fragments covering input rows wm..wm+2, both xh chunks
            uint32_t A[3][2][4];
#pragma unroll
            for (int rr = 0; rr < 3; rr++)
#pragma unroll
                for (int xh = 0; xh < 2; xh++) {
                    uint32_t off = ((uint32_t)((wm + rr) * IW + kw)
                                   + alx + (uint32_t)(xh * 16)) * 128u
                                 + (uint32_t)c * 32u + acol;
                    ldm_x4(A[rr][xh][0], A[rr][xh][1], A[rr][xh][2], A[rr][xh][3],
                           smb + swz(off));
                }
#pragma unroll
            for (int kh = 0; kh < 3; kh++) {
                const uint32_t cb = wbuf + (uint32_t)kh * 8192u + (uint32_t)c * 2048u;
                uint4 B0 = lds128(cb);           // half0: g0,g1
                uint4 B1 = lds128(cb + 512u);    // half1: g2,g3
#pragma unroll
                for (int xh = 0; xh < 2; xh++) {
                    mma16816(acc[xh][0], A[kh][xh], B0.x, B0.y);
                    mma16816(acc[xh][1], A[kh][xh], B0.z, B0.w);
                    mma16816(acc[xh][2], A[kh][xh], B1.x, B1.y);
                    mma16816(acc[xh][3], A[kh][xh], B1.z, B1.w);
                }
            }
        }
        // single-buffered weights: rotate to next kw slice (stall covered by other CTAs)
        if (kw < 2) {
            __syncthreads();                     // all warps done reading slice kw
            const uint4* wp = g_wf + (size_t)(kw + 1) * 1536;
#pragma unroll
            for (int i = tid; i < 1536; i += 256)
                cpasync16(smb + OFF_WB + (uint32_t)i * 16u, wp + i);
            cpasync_commit();
            cpasync_wait0();
            __syncthreads();                     // slice kw+1 visible
        }
    }

    // ---- epilogue: bias + store ----
    const int r0 = lane >> 2, c0 = (lane & 3) * 2;
    float bl[4], bh[4];
#pragma unroll
    for (int g = 0; g < 4; g++) {
        int co = wn * 32 + g * 8 + c0;
        bl[g] = __ldg(bias + co);
        bh[g] = __ldg(bias + co + 1);
    }
    const int y = y0 + wm;
#pragma unroll
    for (int xh = 0; xh < 2; xh++) {
        int xb = x0 + xh * 16;
#pragma unroll
        for (int g = 0; g < 4; g++) {
            int co = wn * 32 + g * 8 + c0;
            float* o0 = out + (((size_t)n * CH + co)     * HH + y) * WW + xb;
            float* o1 = out + (((size_t)n * CH + co + 1) * HH + y) * WW + xb;
            o0[r0]     = acc[xh][g][0] + bl[g];
            o1[r0]     = acc[xh][g][1] + bh[g];
            o0[r0 + 8] = acc[xh][g][2] + bl[g];
            o1[r0 + 8] = acc[xh][g][3] + bh[g];
        }
    }
}

extern "C" void kernel_launch(void* const* d_in, const int* in_sizes, int n_in,
                              void* d_out, int out_size) {
    const float* x    = (const float*)d_in[0];   // [32,64,224,224]
    const float* w    = (const float*)d_in[1];   // [64,64,3,3]
    const float* bias = (const float*)d_in[2];   // [64]
    float* out = (float*)d_out;

    prep_wfrag<<<(3 * 3 * 4 * 2 * 2 * 32 + 255) / 256, 256>>>(w);

    cudaFuncSetAttribute(bconv_mma, cudaFuncAttributeMaxDynamicSharedMemorySize, SMEM_DYN);
    dim3 grid(WW / TPX, HH / TRY, 32);   // (7, 56, 32) = 12544 CTAs
    bconv_mma<<<grid, 256, SMEM_DYN>>>(x, bias, out);
}